// round 1
// baseline (speedup 1.0000x reference)
#include <cuda_runtime.h>

#define T_STEPS 20
#define BETA 0.9f

__global__ void __launch_bounds__(256) xornet_snn_kernel(
    const float4* __restrict__ x4,   // x [B,2] viewed as float4 pairs
    const float*  __restrict__ w1,   // [4,2]
    const float*  __restrict__ w2,   // [1,4]
    float*        __restrict__ out,  // [T, B]
    int B)
{
    const int i  = blockIdx.x * blockDim.x + threadIdx.x;  // group of 4 batch elems
    const int b0 = i * 4;
    if (b0 >= B) return;

    // Load x for 4 consecutive batch elements: 8 floats = 2 float4
    const float4 xa = x4[2 * i + 0];  // b0:{x0,x1}, b1:{x0,x1}
    const float4 xb = x4[2 * i + 1];  // b2:{x0,x1}, b3:{x0,x1}
    const float px0[4] = {xa.x, xa.z, xb.x, xb.z};
    const float px1[4] = {xa.y, xa.w, xb.y, xb.w};

    // Weights (uniform across threads; L1-cached broadcast loads)
    float w1v[4][2];
#pragma unroll
    for (int h = 0; h < 4; h++) {
        w1v[h][0] = __ldg(&w1[2 * h + 0]);
        w1v[h][1] = __ldg(&w1[2 * h + 1]);
    }
    float w2v[4];
#pragma unroll
    for (int h = 0; h < 4; h++) w2v[h] = __ldg(&w2[h]);

    // cur[l][h] = x0*w1[h][0] + x1*w1[h][1], XLA-style fma chain (acc over k)
    float cur[4][4];
#pragma unroll
    for (int l = 0; l < 4; l++)
#pragma unroll
        for (int h = 0; h < 4; h++)
            cur[l][h] = fmaf(px1[l], w1v[h][1], px0[l] * w1v[h][0]);

    // State: membranes and previous spikes (prev spike == this step's reset,
    // bit-identical to (m > 1) since (m-1>0) <=> (m>1) in fp32).
    float m1[4][4] = {};
    float s1[4][4] = {};
    float m2[4]    = {};
    float s2[4]    = {};

    float* outp = out + b0;

#pragma unroll 4
    for (int t = 0; t < T_STEPS; t++) {
#pragma unroll
        for (int l = 0; l < 4; l++) {
#pragma unroll
            for (int h = 0; h < 4; h++) {
                float m = fmaf(BETA, m1[l][h], cur[l][h]) - s1[l][h];
                m1[l][h] = m;
                s1[l][h] = (m - 1.0f > 0.0f) ? 1.0f : 0.0f;
            }
            // out = spk1 . w2  (fma chain in h order, acc starts at s0*w0)
            float o = s1[l][0] * w2v[0];
            o = fmaf(s1[l][1], w2v[1], o);
            o = fmaf(s1[l][2], w2v[2], o);
            o = fmaf(s1[l][3], w2v[3], o);

            float m = fmaf(BETA, m2[l], o) - s2[l];
            m2[l] = m;
            s2[l] = (m - 1.0f > 0.0f) ? 1.0f : 0.0f;
        }
        *reinterpret_cast<float4*>(outp) = make_float4(s2[0], s2[1], s2[2], s2[3]);
        outp += B;  // next timestep plane
    }
}

extern "C" void kernel_launch(void* const* d_in, const int* in_sizes, int n_in,
                              void* d_out, int out_size)
{
    const float* x  = (const float*)d_in[0];   // [B, 2]
    const float* w1 = (const float*)d_in[1];   // [4, 2]
    const float* w2 = (const float*)d_in[2];   // [1, 4]
    float* out      = (float*)d_out;           // [T, B, 1]

    const int B = in_sizes[0] / 2;             // x has B*2 elements
    const int nthreads = B / 4;                // 4 batch elems per thread
    const int block = 256;
    const int grid = (nthreads + block - 1) / block;

    xornet_snn_kernel<<<grid, block>>>(
        (const float4*)x, w1, w2, out, B);
}

// round 4
// speedup vs baseline: 1.0694x; 1.0694x over previous
#include <cuda_runtime.h>

#define T_STEPS 20

typedef unsigned long long u64;

__device__ __forceinline__ u64 pack2(float x, float y) {
    u64 r; asm("mov.b64 %0, {%1, %2};" : "=l"(r) : "f"(x), "f"(y)); return r;
}
__device__ __forceinline__ void unpack2(u64 v, float& x, float& y) {
    asm("mov.b64 {%0, %1}, %2;" : "=f"(x), "=f"(y) : "l"(v));
}
// Packed fma: each half is an independent fma.rn.f32 -> bit-identical to scalar FFMA.
__device__ __forceinline__ u64 ffma2(u64 a, u64 b, u64 c) {
    u64 d; asm("fma.rn.f32x2 %0, %1, %2, %3;" : "=l"(d) : "l"(a), "l"(b), "l"(c)); return d;
}
__device__ __forceinline__ u64 fmul2(u64 a, u64 b) {
    u64 d; asm("mul.rn.f32x2 %0, %1, %2;" : "=l"(d) : "l"(a), "l"(b)); return d;
}
// FSET: float 1.0f/0.0f result of (a > b) in ONE instruction (replaces FSETP+SEL).
__device__ __forceinline__ float fset_gt(float a, float b) {
    float d; asm("set.gt.f32.f32 %0, %1, %2;" : "=f"(d) : "f"(a), "f"(b)); return d;
}

__global__ void __launch_bounds__(256) xornet_snn_kernel(
    const float4* __restrict__ x4,   // x [B,2] as float4 pairs
    const float*  __restrict__ w1,   // [4,2]
    const float*  __restrict__ w2,   // [1,4]
    float*        __restrict__ out,  // [T, B]
    int B)
{
    const int i  = blockIdx.x * blockDim.x + threadIdx.x;  // group of 4 batch elems
    const int b0 = i * 4;
    if (b0 >= B) return;

    const float4 xa = x4[2 * i + 0];  // b0:{x0,x1}, b1:{x0,x1}
    const float4 xb = x4[2 * i + 1];  // b2:{x0,x1}, b3:{x0,x1}
    const float px0[4] = {xa.x, xa.z, xb.x, xb.z};
    const float px1[4] = {xa.y, xa.w, xb.y, xb.w};

    float w1v[4][2];
#pragma unroll
    for (int h = 0; h < 4; h++) {
        w1v[h][0] = __ldg(&w1[2 * h + 0]);
        w1v[h][1] = __ldg(&w1[2 * h + 1]);
    }
    u64 W2[4];
#pragma unroll
    for (int h = 0; h < 4; h++) {
        float w = __ldg(&w2[h]);
        W2[h] = pack2(w, w);
    }

    // cur[p][h]: packed pair of lanes (2p, 2p+1); same fma chain as R1 (bit-identical).
    u64 cur[2][4];
#pragma unroll
    for (int p = 0; p < 2; p++)
#pragma unroll
        for (int h = 0; h < 4; h++) {
            float c0 = fmaf(px1[2 * p + 0], w1v[h][1], px0[2 * p + 0] * w1v[h][0]);
            float c1 = fmaf(px1[2 * p + 1], w1v[h][1], px0[2 * p + 1] * w1v[h][0]);
            cur[p][h] = pack2(c0, c1);
        }

    const u64 BETA2 = pack2(0.9f, 0.9f);
    const u64 NEG1  = pack2(-1.0f, -1.0f);
    const u64 ZERO2 = pack2(0.0f, 0.0f);

    // State: packed membranes + packed previous spikes (prev spike == this step's reset;
    // (m-1>0) <=> (m>1) exactly in fp32, Sterbenz-exact subtraction near 1).
    u64 m1[2][4], s1[2][4], m2[2], s2[2];
#pragma unroll
    for (int p = 0; p < 2; p++) {
#pragma unroll
        for (int h = 0; h < 4; h++) { m1[p][h] = ZERO2; s1[p][h] = ZERO2; }
        m2[p] = ZERO2; s2[p] = ZERO2;
    }

    float* outp = out + b0;

#pragma unroll 4
    for (int t = 0; t < T_STEPS; t++) {
        float so[2][2];  // output spikes for the 4 lanes this step
#pragma unroll
        for (int p = 0; p < 2; p++) {
#pragma unroll
            for (int h = 0; h < 4; h++) {
                // m = beta*m + cur  (packed fma, bit-identical halves)
                u64 m = ffma2(BETA2, m1[p][h], cur[p][h]);
                // m -= s_prev : fma(s,-1,m) == m-1 (single rounding, same as FADD) or m exactly
                m = ffma2(s1[p][h], NEG1, m);
                m1[p][h] = m;
                float lo, hi; unpack2(m, lo, hi);
                s1[p][h] = pack2(fset_gt(lo, 1.0f), fset_gt(hi, 1.0f));
            }
            // o = spk1 . w2 : packed mul + fma chain, same h-order & values as scalar chain
            u64 o = fmul2(s1[p][0], W2[0]);
            o = ffma2(s1[p][1], W2[1], o);
            o = ffma2(s1[p][2], W2[2], o);
            o = ffma2(s1[p][3], W2[3], o);

            u64 m = ffma2(BETA2, m2[p], o);
            m = ffma2(s2[p], NEG1, m);
            m2[p] = m;
            float lo, hi; unpack2(m, lo, hi);
            so[p][0] = fset_gt(lo, 1.0f);
            so[p][1] = fset_gt(hi, 1.0f);
            s2[p] = pack2(so[p][0], so[p][1]);
        }
        *reinterpret_cast<float4*>(outp) =
            make_float4(so[0][0], so[0][1], so[1][0], so[1][1]);
        outp += B;  // next timestep plane
    }
}

extern "C" void kernel_launch(void* const* d_in, const int* in_sizes, int n_in,
                              void* d_out, int out_size)
{
    const float* x  = (const float*)d_in[0];   // [B, 2]
    const float* w1 = (const float*)d_in[1];   // [4, 2]
    const float* w2 = (const float*)d_in[2];   // [1, 4]
    float* out      = (float*)d_out;           // [T, B, 1]

    const int B = in_sizes[0] / 2;
    const int nthreads = B / 4;
    const int block = 256;
    const int grid = (nthreads + block - 1) / block;

    xornet_snn_kernel<<<grid, block>>>((const float4*)x, w1, w2, out, B);
}